// round 13
// baseline (speedup 1.0000x reference)
#include <cuda_runtime.h>
#include <cuda_bf16.h>

// Problem constants (fixed by the dataset: b=2, c=8, h=w=128, P=3, Wn=7)
#define IMG_H 128
#define IMG_W 128
#define NCH 8
#define NB 2
#define PL (IMG_H*IMG_W)

// 16x16 tile, one CTA per SM (grid 128 <= 148 SMs), 4 slices x 256 px
#define TY 16
#define TX 16
#define NPIX (TY*TX)           // 256 pixels per tile
#define NSLICE 4
#define NTHREADS (NPIX*NSLICE) // 1024
#define HP 4                   // phi halo
#define HG 3                   // g halo
#define PH (TY + 2*HP)         // 24
#define PW (TX + 2*HP)         // 24
#define GH (TY + 2*HG)         // 22
#define GW (TX + 2*HG)         // 22
#define NPHI (PH*PW)           // 576
#define NG (GH*GW)             // 484

// Correlation map: tile dilated by 1 (patch radius)
#define CW 18
#define CHh 18
#define CN (CHh*CW)            // 324
#define CNP 328                // padded stride
#define KMAX 13                // maps per slice (slice 0: 13, others: 12)

// H map: horizontal 3-sums, 18 rows x 16 cols
#define HW 16
#define HN (CHh*HW)            // 288
#define HPAIRS (CHh*HW/2)      // 144
#define HUNITS (KMAX*HPAIRS)   // 1872

// ---- dynamic shared memory layout (bytes) ----
#define OFF_PHIA 0
#define OFF_PHIB (OFF_PHIA + NPHI*16)            // 9216
#define OFF_GA   (OFF_PHIB + NPHI*16)            // 18432
#define OFF_GB   (OFF_GA   + NG*16)              // 26176
#define OFF_CS   (OFF_GB   + NG*16)              // 33920
#define OFF_WPK  (OFF_CS   + NSLICE*KMAX*CNP*4)  // 102144
#define OFF_HS   (OFF_WPK  + 512)                // 102656
#define SMEM_TOTAL (OFF_HS + NSLICE*KMAX*HN*4)   // 162560

#define BARS(id) asm volatile("bar.sync %0, %1;" :: "r"(id), "r"(256) : "memory")

#define MUL2(out, a, b) \
    asm("mul.rn.f32x2 %0, %1, %2;" : "=l"(out) : "l"(a), "l"(b))
#define FMA2(out, a, b, c) \
    asm("fma.rn.f32x2 %0, %1, %2, %3;" : "=l"(out) : "l"(a), "l"(b), "l"(c))
#define PACK2(out, lo, hi) \
    asm("mov.b64 %0, {%1, %2};" : "=l"(out) : "f"(lo), "f"(hi))
#define UNPACK2(lo, hi, in) \
    asm("mov.b64 {%0, %1}, %2;" : "=f"(lo), "=f"(hi) : "l"(in))

// ---- per-slice specialized produce + H stage (j = S_+4k is compile-time) ----
#define PRODUCE_AND_H(S_) do {                                                \
    float* Cme = Csb + (S_) * (KMAX*CNP);                                     \
    float* Hme = Hsb + (S_) * (KMAX*HN);                                      \
    _Pragma("unroll")                                                         \
    for (int k = 0; k < KMAX; k++) {                                          \
        const int j = (S_) + 4*k;                                             \
        if (j < 49) {                                                         \
            const int off = (j/7 - 3)*PW + (j%7 - 3);                         \
            {                                                                 \
                ulonglong2 wa = *(const ulonglong2*)&phiA[cell0 + off];       \
                ulonglong2 wb = *(const ulonglong2*)&phiB[cell0 + off];       \
                unsigned long long acc;                                       \
                MUL2(acc, v0p0, wa.x);                                        \
                FMA2(acc, v0p1, wa.y, acc);                                   \
                FMA2(acc, v0p2, wb.x, acc);                                   \
                FMA2(acc, v0p3, wb.y, acc);                                   \
                float lo, hi; UNPACK2(lo, hi, acc);                           \
                Cme[k*CNP + p0] = lo + hi;                                    \
            }                                                                 \
            if (has1) {                                                       \
                ulonglong2 wa = *(const ulonglong2*)&phiA[cell1 + off];       \
                ulonglong2 wb = *(const ulonglong2*)&phiB[cell1 + off];       \
                unsigned long long acc;                                       \
                MUL2(acc, v1p0, wa.x);                                        \
                FMA2(acc, v1p1, wa.y, acc);                                   \
                FMA2(acc, v1p2, wb.x, acc);                                   \
                FMA2(acc, v1p3, wb.y, acc);                                   \
                float lo, hi; UNPACK2(lo, hi, acc);                           \
                Cme[k*CNP + p1] = lo + hi;                                    \
            }                                                                 \
        }                                                                     \
    }                                                                         \
    BARS((S_) + 1);                                                           \
    _Pragma("unroll")                                                         \
    for (int i = 0; i < 8; i++) {                                             \
        const int uu = px + NPIX*i;                                           \
        if (uu < HUNITS) {                                                    \
            const int k2 = uu / HPAIRS;                                       \
            const int pr = uu - k2*HPAIRS;                                    \
            const int r  = pr >> 3;                                           \
            const int cq = (pr & 7) << 1;                                     \
            const float2 a2 = *(const float2*)&Cme[k2*CNP + r*CW + cq];       \
            const float2 b2 = *(const float2*)&Cme[k2*CNP + r*CW + cq + 2];   \
            *(float2*)&Hme[k2*HN + r*HW + cq] =                               \
                make_float2(a2.x + a2.y + b2.x, a2.y + b2.x + b2.y);          \
        }                                                                     \
    }                                                                         \
} while (0)

// ---- per-slice specialized fused pass (no barriers inside) ----
#define FUSED(S_) do {                                                        \
    const float* Hme = Hsb + (S_) * (KMAX*HN);                                \
    _Pragma("unroll")                                                         \
    for (int k = 0; k < KMAX; k++) {                                          \
        const int j = (S_) + 4*k;                                             \
        if (j < 49) {                                                         \
            const int offg = (j/7)*GW + (j%7);                                \
            const float* hb = &Hme[k*HN + ty*HW + tx];                        \
            float v = hb[0] + hb[HW] + hb[2*HW];                              \
            float l = ((mask49 >> j) & 1ULL) ? v : 0.f;                       \
            float e = __expf(l - b);                                          \
            S += e;                                                           \
            unsigned long long e2; PACK2(e2, e, e);                           \
            const int gi = gbase + offg;                                      \
            ulonglong2 g0 = *(const ulonglong2*)&gA[gi];                      \
            ulonglong2 g1 = *(const ulonglong2*)&gB[gi];                      \
            FMA2(o01, e2, g0.x, o01);                                         \
            FMA2(o23, e2, g0.y, o23);                                         \
            FMA2(o45, e2, g1.x, o45);                                         \
            FMA2(o67, e2, g1.y, o67);                                         \
        }                                                                     \
    }                                                                         \
} while (0)

__global__ __launch_bounds__(NTHREADS, 1)
void attn_spec_kernel(const float* __restrict__ u,
                      const float* __restrict__ pan,
                      const float* __restrict__ Wphi,
                      const float* __restrict__ Wg,
                      float* __restrict__ out)
{
    extern __shared__ __align__(16) char smem_raw[];
    float4* phiA = (float4*)(smem_raw + OFF_PHIA);
    float4* phiB = (float4*)(smem_raw + OFF_PHIB);
    float4* gA   = (float4*)(smem_raw + OFF_GA);
    float4* gB   = (float4*)(smem_raw + OFF_GB);
    float*  Csb  = (float*)(smem_raw + OFF_CS);
    unsigned long long* wpk = (unsigned long long*)(smem_raw + OFF_WPK); // [64]
    float*  Hsb  = (float*)(smem_raw + OFF_HS);

    const int tid  = threadIdx.x;
    const int bimg = blockIdx.z;
    const int y0   = blockIdx.y * TY;
    const int x0   = blockIdx.x * TX;

    const float* panb = pan + (size_t)bimg * NCH * PL;
    const float* ub   = u   + (size_t)bimg * NCH * PL;

    // ---- prologue: issue input LDGs FIRST (in flight across the weight sync) ----
    const bool doPhi = (tid < NPHI);
    const int  gcell = (tid >= NPHI) ? (tid - NPHI)
                     : (tid < NG - (NTHREADS - NPHI) ? tid + (NTHREADS - NPHI) : -1);

    float pv[NCH], uv[NCH];
    if (doPhi) {
        int r = tid / PW, c = tid % PW;
        int yy = y0 - HP + r, xx = x0 - HP + c;
        bool in = ((unsigned)yy < IMG_H) && ((unsigned)xx < IMG_W);
        #pragma unroll
        for (int ch = 0; ch < NCH; ch++)
            pv[ch] = in ? panb[ch*PL + yy*IMG_W + xx] : 0.f;
    }
    if (gcell >= 0) {
        int r = gcell / GW, c = gcell % GW;
        int yy = y0 - HG + r, xx = x0 - HG + c;
        bool in = ((unsigned)yy < IMG_H) && ((unsigned)xx < IMG_W);
        #pragma unroll
        for (int ch = 0; ch < NCH; ch++)
            uv[ch] = in ? ub[ch*PL + yy*IMG_W + xx] : 0.f;
    }

    // packed weight pairs: wpk[ci*4+op] = (W[2op][ci], W[2op+1][ci])
    if (tid < 64) {
        const float* W = (tid < 32) ? Wphi : Wg;
        int t  = tid & 31;
        int ci = t >> 2, op = t & 3;
        float wlo = W[(2*op  )*NCH + ci];
        float whi = W[(2*op+1)*NCH + ci];
        unsigned long long wp; PACK2(wp, wlo, whi);
        wpk[tid] = wp;
    }
    __syncthreads();

    if (doPhi) {
        unsigned long long acc[4];
        #pragma unroll
        for (int ci = 0; ci < NCH; ci++) {
            unsigned long long pvx2; PACK2(pvx2, pv[ci], pv[ci]);
            #pragma unroll
            for (int op = 0; op < 4; op++) {
                if (ci == 0) { MUL2(acc[op], wpk[op], pvx2); }
                else         { FMA2(acc[op], wpk[ci*4+op], pvx2, acc[op]); }
            }
        }
        *(ulonglong2*)&phiA[tid] = make_ulonglong2(acc[0], acc[1]);
        *(ulonglong2*)&phiB[tid] = make_ulonglong2(acc[2], acc[3]);
    }
    if (gcell >= 0) {
        unsigned long long acc[4];
        #pragma unroll
        for (int ci = 0; ci < NCH; ci++) {
            unsigned long long uvx2; PACK2(uvx2, uv[ci], uv[ci]);
            #pragma unroll
            for (int op = 0; op < 4; op++) {
                if (ci == 0) { MUL2(acc[op], wpk[32 + op], uvx2); }
                else         { FMA2(acc[op], wpk[32 + ci*4+op], uvx2, acc[op]); }
            }
        }
        *(ulonglong2*)&gA[gcell] = make_ulonglong2(acc[0], acc[1]);
        *(ulonglong2*)&gB[gcell] = make_ulonglong2(acc[2], acc[3]);
    }
    __syncthreads();

    const int px    = tid & (NPIX-1);      // pixel within tile (0..255)
    const int slice = tid >> 8;            // owns offsets j = slice + 4k
    const int ty = px >> 4, tx = px & 15;
    const int gy = y0 + ty, gx = x0 + tx;

    // correlation positions: primary = px; extras (324-256=68) in low warps
    const int p0    = px;
    const int cell0 = (p0/CW + 3) * PW + (p0%CW + 3);
    const bool has1 = (px < CN - NPIX);    // px < 68
    const int p1    = px + NPIX;
    const int cell1 = has1 ? (p1/CW + 3) * PW + (p1%CW + 3) : cell0;

    unsigned long long v0p0, v0p1, v0p2, v0p3, v1p0, v1p1, v1p2, v1p3;
    {
        ulonglong2 a = *(const ulonglong2*)&phiA[cell0];
        ulonglong2 b2 = *(const ulonglong2*)&phiB[cell0];
        v0p0 = a.x; v0p1 = a.y; v0p2 = b2.x; v0p3 = b2.y;
        ulonglong2 a1 = *(const ulonglong2*)&phiA[cell1];
        ulonglong2 b1 = *(const ulonglong2*)&phiB[cell1];
        v1p0 = a1.x; v1p1 = a1.y; v1p2 = b1.x; v1p3 = b1.y;
    }

    // ---- produce + H, specialized per slice ----
    switch (slice) {
        case 0: PRODUCE_AND_H(0); break;
        case 1: PRODUCE_AND_H(1); break;
        case 2: PRODUCE_AND_H(2); break;
        default: PRODUCE_AND_H(3); break;
    }
    __syncthreads();   // full: all slices need slice0's H (k=6 <-> j=24, delta=0)

    // ---- per-pixel shift b = self-logit ||theta_q||^2 (box-sum of C_0) ----
    float b;
    {
        const float* h0 = &Hsb[6*HN + ty*HW + tx];
        b = h0[0] + h0[HW] + h0[2*HW];
    }

    // ---- 49-bit OOB mask: bit j set iff window pixel j is inside the image ----
    unsigned long long mask49;
    {
        int ym = 0, xm = 0;
        #pragma unroll
        for (int d = 0; d < 7; d++) {
            ym |= (int)((unsigned)(gy + d - 3) < IMG_H) << d;
            xm |= (int)((unsigned)(gx + d - 3) < IMG_W) << d;
        }
        mask49 = 0ULL;
        #pragma unroll
        for (int d = 0; d < 7; d++)
            mask49 |= (unsigned long long)(((ym >> d) & 1) ? xm : 0) << (7*d);
    }

    // ---- fused pass: logit -> exp(l-b) -> accumulate, specialized per slice ----
    const int gbase = ty * GW + tx;
    float S = 0.f;
    unsigned long long o01 = 0ULL, o23 = 0ULL, o45 = 0ULL, o67 = 0ULL;
    switch (slice) {
        case 0: FUSED(0); break;
        case 1: FUSED(1); break;
        case 2: FUSED(2); break;
        default: FUSED(3); break;
    }

    // ---- merge: plain sums across 4 slices (common shift b), packed scratch ----
    __syncthreads();                      // all slices done with Cs/Hs
    float* redS = Csb;                                  // [1024] floats
    unsigned long long* redO = (unsigned long long*)(Csb + NTHREADS); // [4][1024]
    redS[tid] = S;
    redO[0*NTHREADS + tid] = o01;
    redO[1*NTHREADS + tid] = o23;
    redO[2*NTHREADS + tid] = o45;
    redO[3*NTHREADS + tid] = o67;
    __syncthreads();

    {
        float St = redS[0*NPIX + px] + redS[1*NPIX + px]
                 + redS[2*NPIX + px] + redS[3*NPIX + px];
        float inv = __fdividef(1.f, St);

        // slice s merges channel-pair s (o-plane s): 4 LDS.64 + 2 STG
        const unsigned long long* rp = redO + slice*NTHREADS + px;
        float a0, a1, t0, t1;
        UNPACK2(a0, a1, rp[0*NPIX]);
        UNPACK2(t0, t1, rp[1*NPIX]);  a0 += t0; a1 += t1;
        UNPACK2(t0, t1, rp[2*NPIX]);  a0 += t0; a1 += t1;
        UNPACK2(t0, t1, rp[3*NPIX]);  a0 += t0; a1 += t1;

        const int ch0 = 2*slice;
        float* ob = out + (size_t)bimg*NCH*PL + (size_t)gy*IMG_W + gx;
        ob[ch0*PL]     = a0 * inv;
        ob[(ch0+1)*PL] = a1 * inv;
    }
}

extern "C" void kernel_launch(void* const* d_in, const int* in_sizes, int n_in,
                              void* d_out, int out_size)
{
    const float* u    = (const float*)d_in[0];
    const float* pan  = (const float*)d_in[1];
    const float* Wphi = (const float*)d_in[2];
    const float* Wg   = (const float*)d_in[3];
    float* out = (float*)d_out;

    cudaFuncSetAttribute(attn_spec_kernel,
                         cudaFuncAttributeMaxDynamicSharedMemorySize, SMEM_TOTAL);

    dim3 grid(IMG_W / TX, IMG_H / TY, NB);   // (8, 8, 2) = 128 blocks, 1 per SM
    dim3 block(NTHREADS);                     // 1024
    attn_spec_kernel<<<grid, block, SMEM_TOTAL>>>(u, pan, Wphi, Wg, out);
}